// round 1
// baseline (speedup 1.0000x reference)
#include <cuda_runtime.h>
#include <math.h>

#define TT      8192      // total tokens (B*L)
#define LSEQ    4096
#define NBATCH  2
#define DMODEL  2048
#define DINNER  4096
#define DSTATE  128
#define DCONV   4
#define NH      64
#define HD      64
#define CHUNKSZ 64
#define NCHUNK  64        // chunks per batch
#define CONVDIM 4352      // DINNER + 2*DSTATE
#define DPROJ   8512      // 2*DINNER + 2*DSTATE + NH
#define DT_OFF  8448      // DPROJ - NH

// ---------------- scratch (device globals; no runtime allocation) -------------
__device__ float gZX[(size_t)TT * DPROJ];                         // in-proj output (z | xBC | dt)
__device__ float gXC[(size_t)TT * CONVDIM];                       // conv+silu output
__device__ float gYb[(size_t)TT * DINNER];                        // y buffer
__device__ float gStates[(size_t)NBATCH * NCHUNK * NH * HD * DSTATE]; // chunk states -> prefix states
__device__ float gDt[TT * NH];
__device__ float gDalog[TT * NH];
__device__ float gAsum[NBATCH * NCHUNK * NH];

// ---------------- GEMM: C[m,n] = sum_k A[m,k] * B[n,k]  (both K-major) --------
// BM=BN=128, BK=16, 256 threads, 8x8 per thread.
#define GBM 128
#define GBN 128
#define GBK 16
#define GLDS 132   // padded stride for smem tiles

__global__ __launch_bounds__(256)
void gemm_nt_kernel(const float* __restrict__ A, const float* __restrict__ B,
                    float* __restrict__ C, int M, int N, int K)
{
    __shared__ float As[GBK][GLDS];
    __shared__ float Bs[GBK][GLDS];

    const int tid = threadIdx.x;
    const int m0 = blockIdx.y * GBM;
    const int n0 = blockIdx.x * GBN;
    const int tx = tid & 15;
    const int ty = tid >> 4;

    const int lr  = tid >> 2;        // 0..63
    const int lc4 = (tid & 3) << 2;  // 0,4,8,12

    float acc[8][8];
#pragma unroll
    for (int i = 0; i < 8; i++)
#pragma unroll
        for (int j = 0; j < 8; j++) acc[i][j] = 0.f;

    for (int k0 = 0; k0 < K; k0 += GBK) {
        // load A tile (always in range: M,K multiples of tile)
#pragma unroll
        for (int rr = 0; rr < 2; rr++) {
            int m = m0 + lr + rr * 64;
            float4 v = *(const float4*)(A + (size_t)m * K + k0 + lc4);
            As[lc4 + 0][lr + rr * 64] = v.x;
            As[lc4 + 1][lr + rr * 64] = v.y;
            As[lc4 + 2][lr + rr * 64] = v.z;
            As[lc4 + 3][lr + rr * 64] = v.w;
        }
        // load B tile (guard rows n >= N)
#pragma unroll
        for (int rr = 0; rr < 2; rr++) {
            int n = n0 + lr + rr * 64;
            float4 v = make_float4(0.f, 0.f, 0.f, 0.f);
            if (n < N) v = *(const float4*)(B + (size_t)n * K + k0 + lc4);
            Bs[lc4 + 0][lr + rr * 64] = v.x;
            Bs[lc4 + 1][lr + rr * 64] = v.y;
            Bs[lc4 + 2][lr + rr * 64] = v.z;
            Bs[lc4 + 3][lr + rr * 64] = v.w;
        }
        __syncthreads();

#pragma unroll
        for (int kk = 0; kk < GBK; kk++) {
            float ra[8], rb[8];
#pragma unroll
            for (int i = 0; i < 8; i++) ra[i] = As[kk][ty * 8 + i];
#pragma unroll
            for (int j = 0; j < 8; j++) rb[j] = Bs[kk][tx * 8 + j];
#pragma unroll
            for (int i = 0; i < 8; i++)
#pragma unroll
                for (int j = 0; j < 8; j++) acc[i][j] += ra[i] * rb[j];
        }
        __syncthreads();
    }

#pragma unroll
    for (int i = 0; i < 8; i++) {
        int m = m0 + ty * 8 + i;
#pragma unroll
        for (int j = 0; j < 8; j++) {
            int n = n0 + tx * 8 + j;
            if (n < N) C[(size_t)m * N + n] = acc[i][j];
        }
    }
}

// ---------------- dt = softplus(dt_raw + bias); dalog = dt * (-exp(A_log)) ----
__global__ __launch_bounds__(256)
void dt_kernel(const float* __restrict__ dt_bias, const float* __restrict__ A_log)
{
    int i = blockIdx.x * blockDim.x + threadIdx.x;
    if (i >= TT * NH) return;
    int h = i & (NH - 1);
    int t = i >> 6;
    float x = gZX[(size_t)t * DPROJ + DT_OFF + h] + dt_bias[h];
    float sp = (x > 20.f) ? x : log1pf(__expf(x));
    float A = -__expf(A_log[h]);
    gDt[i] = sp;
    gDalog[i] = sp * A;
}

// ---------------- causal conv1d (k=4) + bias + SiLU ---------------------------
__global__ __launch_bounds__(256)
void conv_kernel(const float* __restrict__ conv_w, const float* __restrict__ conv_b)
{
    int idx = blockIdx.x * blockDim.x + threadIdx.x;     // float4 index
    const int per_tok = CONVDIM / 4;
    if (idx >= TT * per_tok) return;
    int t  = idx / per_tok;
    int c4 = (idx - t * per_tok) * 4;
    int l  = t & (LSEQ - 1);

    float acc0 = conv_b[c4 + 0];
    float acc1 = conv_b[c4 + 1];
    float acc2 = conv_b[c4 + 2];
    float acc3 = conv_b[c4 + 3];
#pragma unroll
    for (int k = 0; k < DCONV; k++) {
        int lk = l - (DCONV - 1) + k;
        if (lk >= 0) {
            const float4 v = *(const float4*)&gZX[(size_t)(t - (DCONV - 1) + k) * DPROJ + DINNER + c4];
            acc0 += v.x * conv_w[(c4 + 0) * DCONV + k];
            acc1 += v.y * conv_w[(c4 + 1) * DCONV + k];
            acc2 += v.z * conv_w[(c4 + 2) * DCONV + k];
            acc3 += v.w * conv_w[(c4 + 3) * DCONV + k];
        }
    }
    float* o = &gXC[(size_t)t * CONVDIM + c4];
    o[0] = acc0 / (1.f + __expf(-acc0));
    o[1] = acc1 / (1.f + __expf(-acc1));
    o[2] = acc2 / (1.f + __expf(-acc2));
    o[3] = acc3 / (1.f + __expf(-acc3));
}

// ---------------- per-(chunk, head): Y_diag + local chunk states --------------
#define LDN 129
#define LDP 65

__global__ __launch_bounds__(256)
void chunk_kernel()
{
    extern __shared__ float sm[];
    float* sB   = sm;                 // 64 x LDN
    float* sC   = sB + 64 * LDN;      // 64 x LDN
    float* sX   = sC + 64 * LDN;      // 64 x LDP   (x * dt)
    float* sM   = sX + 64 * LDP;      // 64 x LDP
    float* sAcs = sM + 64 * LDP;      // 64
    float* sDec = sAcs + 64;          // 64

    const int bc = blockIdx.x;        // b*NCHUNK + c
    const int h  = blockIdx.y;
    const int tid = threadIdx.x;
    const int t0 = bc * CHUNKSZ;      // == b*LSEQ + c*CHUNKSZ

    if (tid < 64) sAcs[tid] = gDalog[(size_t)(t0 + tid) * NH + h];
    __syncthreads();
    if (tid == 0) {
        float s = 0.f;
        for (int l = 0; l < 64; l++) { s += sAcs[l]; sAcs[l] = s; }
    }
    __syncthreads();
    if (tid < 64) sDec[tid] = __expf(sAcs[63] - sAcs[tid]);

    // load B, C tiles (64 x 128)
    for (int i = tid; i < 2048; i += 256) {
        int s  = i >> 5;
        int c4 = (i & 31) << 2;
        const float* row = &gXC[(size_t)(t0 + s) * CONVDIM];
        float4 vb = *(const float4*)(row + DINNER + c4);
        float4 vc = *(const float4*)(row + DINNER + DSTATE + c4);
        sB[s * LDN + c4 + 0] = vb.x; sB[s * LDN + c4 + 1] = vb.y;
        sB[s * LDN + c4 + 2] = vb.z; sB[s * LDN + c4 + 3] = vb.w;
        sC[s * LDN + c4 + 0] = vc.x; sC[s * LDN + c4 + 1] = vc.y;
        sC[s * LDN + c4 + 2] = vc.z; sC[s * LDN + c4 + 3] = vc.w;
    }
    // load X (x * dt), 64 x 64
    for (int i = tid; i < 1024; i += 256) {
        int s  = i >> 4;
        int c4 = (i & 15) << 2;
        float d = gDt[(size_t)(t0 + s) * NH + h];
        float4 v = *(const float4*)(&gXC[(size_t)(t0 + s) * CONVDIM + h * HD + c4]);
        sX[s * LDP + c4 + 0] = v.x * d; sX[s * LDP + c4 + 1] = v.y * d;
        sX[s * LDP + c4 + 2] = v.z * d; sX[s * LDP + c4 + 3] = v.w * d;
    }
    __syncthreads();

    const int tx = tid & 15;
    const int ty = tid >> 4;

    // M = C * B^T  (64x64, K=128)
    {
        float acc[4][4];
#pragma unroll
        for (int i = 0; i < 4; i++)
#pragma unroll
            for (int j = 0; j < 4; j++) acc[i][j] = 0.f;
        for (int n = 0; n < 128; n++) {
            float a[4], b[4];
#pragma unroll
            for (int i = 0; i < 4; i++) a[i] = sC[(ty * 4 + i) * LDN + n];
#pragma unroll
            for (int j = 0; j < 4; j++) b[j] = sB[(tx * 4 + j) * LDN + n];
#pragma unroll
            for (int i = 0; i < 4; i++)
#pragma unroll
                for (int j = 0; j < 4; j++) acc[i][j] += a[i] * b[j];
        }
#pragma unroll
        for (int i = 0; i < 4; i++)
#pragma unroll
            for (int j = 0; j < 4; j++)
                sM[(ty * 4 + i) * LDP + tx * 4 + j] = acc[i][j];
    }
    __syncthreads();

    // apply L matrix: M[l,s] *= exp(acs[l]-acs[s]) for s<=l, else 0
    for (int i = tid; i < 4096; i += 256) {
        int l = i >> 6, s = i & 63;
        float v = (s <= l) ? sM[l * LDP + s] * __expf(sAcs[l] - sAcs[s]) : 0.f;
        sM[l * LDP + s] = v;
    }
    __syncthreads();

    // Y_diag = (M .* L) @ X   (64x64, K=64)
    {
        float acc[4][4];
#pragma unroll
        for (int i = 0; i < 4; i++)
#pragma unroll
            for (int j = 0; j < 4; j++) acc[i][j] = 0.f;
        for (int s = 0; s < 64; s++) {
            float w[4], xv[4];
#pragma unroll
            for (int i = 0; i < 4; i++) w[i] = sM[(ty * 4 + i) * LDP + s];
#pragma unroll
            for (int j = 0; j < 4; j++) xv[j] = sX[s * LDP + tx * 4 + j];
#pragma unroll
            for (int i = 0; i < 4; i++)
#pragma unroll
                for (int j = 0; j < 4; j++) acc[i][j] += w[i] * xv[j];
        }
#pragma unroll
        for (int i = 0; i < 4; i++) {
            int l = ty * 4 + i;
#pragma unroll
            for (int j = 0; j < 4; j++) {
                int p = tx * 4 + j;
                gYb[(size_t)(t0 + l) * DINNER + h * HD + p] = acc[i][j];
            }
        }
    }

    // chunk-local states[p,n] = sum_s X[s,p] * dec[s] * B[s,n]  (64 x 128)
    {
        float st[4][8];
#pragma unroll
        for (int i = 0; i < 4; i++)
#pragma unroll
            for (int j = 0; j < 8; j++) st[i][j] = 0.f;
        const int pb = ty * 4, nb = tx * 8;
        for (int s = 0; s < 64; s++) {
            float d = sDec[s];
            float xv[4], bv[8];
#pragma unroll
            for (int i = 0; i < 4; i++) xv[i] = sX[s * LDP + pb + i] * d;
#pragma unroll
            for (int j = 0; j < 8; j++) bv[j] = sB[s * LDN + nb + j];
#pragma unroll
            for (int i = 0; i < 4; i++)
#pragma unroll
                for (int j = 0; j < 8; j++) st[i][j] += xv[i] * bv[j];
        }
        size_t base = ((size_t)bc * NH + h) * (HD * DSTATE);
#pragma unroll
        for (int i = 0; i < 4; i++)
#pragma unroll
            for (int j = 0; j < 8; j++)
                gStates[base + (size_t)(pb + i) * DSTATE + nb + j] = st[i][j];
    }

    if (tid == 0) gAsum[bc * NH + h] = sAcs[63];
}

// ---------------- inter-chunk scan (sequential over chunks) -------------------
__global__ __launch_bounds__(512)
void scan_kernel()
{
    const int bh = blockIdx.x;        // b*NH + h
    const int b = bh >> 6, h = bh & 63;
    const int tid = threadIdx.x;
    const int off = tid * 16;

    float4 prev[4];
#pragma unroll
    for (int q = 0; q < 4; q++) prev[q] = make_float4(0.f, 0.f, 0.f, 0.f);

    for (int c = 0; c < NCHUNK; c++) {
        int bc = b * NCHUNK + c;
        size_t base = ((size_t)bc * NH + h) * (HD * DSTATE) + off;
        float dec = __expf(gAsum[bc * NH + h]);
        float4 cur[4];
#pragma unroll
        for (int q = 0; q < 4; q++) cur[q] = *(float4*)&gStates[base + q * 4];
#pragma unroll
        for (int q = 0; q < 4; q++) *(float4*)&gStates[base + q * 4] = prev[q];
#pragma unroll
        for (int q = 0; q < 4; q++) {
            prev[q].x = prev[q].x * dec + cur[q].x;
            prev[q].y = prev[q].y * dec + cur[q].y;
            prev[q].z = prev[q].z * dec + cur[q].z;
            prev[q].w = prev[q].w * dec + cur[q].w;
        }
    }
}

// ---------------- Y_off + D-skip + SiLU(z) gating ------------------------------
__global__ __launch_bounds__(256)
void yoff_kernel(const float* __restrict__ Dparam)
{
    extern __shared__ float sm[];
    float* sC   = sm;                  // 64 x LDN
    float* sSt  = sC + 64 * LDN;       // 64 x LDN  (p-major, n inner)
    float* sAcs = sSt + 64 * LDN;      // 64

    const int bc = blockIdx.x;
    const int h  = blockIdx.y;
    const int tid = threadIdx.x;
    const int t0 = bc * CHUNKSZ;

    if (tid < 64) sAcs[tid] = gDalog[(size_t)(t0 + tid) * NH + h];
    __syncthreads();
    if (tid == 0) {
        float s = 0.f;
        for (int l = 0; l < 64; l++) { s += sAcs[l]; sAcs[l] = s; }
    }

    for (int i = tid; i < 2048; i += 256) {
        int s  = i >> 5;
        int c4 = (i & 31) << 2;
        float4 vc = *(const float4*)(&gXC[(size_t)(t0 + s) * CONVDIM + DINNER + DSTATE + c4]);
        sC[s * LDN + c4 + 0] = vc.x; sC[s * LDN + c4 + 1] = vc.y;
        sC[s * LDN + c4 + 2] = vc.z; sC[s * LDN + c4 + 3] = vc.w;
        float4 vs = *(const float4*)(&gStates[(((size_t)bc * NH + h) * HD + s) * DSTATE + c4]);
        sSt[s * LDN + c4 + 0] = vs.x; sSt[s * LDN + c4 + 1] = vs.y;
        sSt[s * LDN + c4 + 2] = vs.z; sSt[s * LDN + c4 + 3] = vs.w;
    }
    __syncthreads();

    const int tx = tid & 15;
    const int ty = tid >> 4;

    float acc[4][4];
#pragma unroll
    for (int i = 0; i < 4; i++)
#pragma unroll
        for (int j = 0; j < 4; j++) acc[i][j] = 0.f;
    for (int n = 0; n < 128; n++) {
        float cv[4], sv[4];
#pragma unroll
        for (int i = 0; i < 4; i++) cv[i] = sC[(ty * 4 + i) * LDN + n];
#pragma unroll
        for (int j = 0; j < 4; j++) sv[j] = sSt[(tx * 4 + j) * LDN + n];
#pragma unroll
        for (int i = 0; i < 4; i++)
#pragma unroll
            for (int j = 0; j < 4; j++) acc[i][j] += cv[i] * sv[j];
    }

    const float Dh = Dparam[h];
#pragma unroll
    for (int i = 0; i < 4; i++) {
        int l = ty * 4 + i;
        float sdo = __expf(sAcs[l]);
        size_t tz = (size_t)(t0 + l);
#pragma unroll
        for (int j = 0; j < 4; j++) {
            int p = tx * 4 + j;
            float x = gXC[tz * CONVDIM + h * HD + p];
            float z = gZX[tz * DPROJ + h * HD + p];
            float y = gYb[tz * DINNER + h * HD + p] + sdo * acc[i][j] + x * Dh;
            y *= z / (1.f + __expf(-z));
            gYb[tz * DINNER + h * HD + p] = y;
        }
    }
}

// ---------------- RMSNorm over DINNER ------------------------------------------
__global__ __launch_bounds__(256)
void rms_kernel(const float* __restrict__ norm_w)
{
    const int t = blockIdx.x;
    const int tid = threadIdx.x;
    float* y = &gYb[(size_t)t * DINNER];

    float ss = 0.f;
    for (int i = tid * 4; i < DINNER; i += 256 * 4) {
        float4 v = *(const float4*)(y + i);
        ss += v.x * v.x + v.y * v.y + v.z * v.z + v.w * v.w;
    }
#pragma unroll
    for (int o = 16; o > 0; o >>= 1) ss += __shfl_down_sync(0xffffffffu, ss, o);

    __shared__ float red[8];
    if ((tid & 31) == 0) red[tid >> 5] = ss;
    __syncthreads();
    if (tid == 0) {
        float tot = 0.f;
#pragma unroll
        for (int w = 0; w < 8; w++) tot += red[w];
        red[0] = rsqrtf(tot / (float)DINNER + 1e-5f);
    }
    __syncthreads();
    const float scale = red[0];

    for (int i = tid * 4; i < DINNER; i += 256 * 4) {
        float4 v = *(const float4*)(y + i);
        float4 w = *(const float4*)(norm_w + i);
        v.x *= scale * w.x; v.y *= scale * w.y;
        v.z *= scale * w.z; v.w *= scale * w.w;
        *(float4*)(y + i) = v;
    }
}

// ---------------- launch ---------------------------------------------------------
extern "C" void kernel_launch(void* const* d_in, const int* in_sizes, int n_in,
                              void* d_out, int out_size)
{
    const float* u       = (const float*)d_in[0];
    const float* W_in    = (const float*)d_in[1];
    const float* conv_w  = (const float*)d_in[2];
    const float* conv_b  = (const float*)d_in[3];
    const float* dt_bias = (const float*)d_in[4];
    const float* A_log   = (const float*)d_in[5];
    const float* Dparam  = (const float*)d_in[6];
    const float* norm_w  = (const float*)d_in[7];
    const float* W_out   = (const float*)d_in[8];
    float* out = (float*)d_out;

    void *pZX, *pYb;
    cudaGetSymbolAddress(&pZX, gZX);
    cudaGetSymbolAddress(&pYb, gYb);

    const int chunk_smem = (2 * 64 * LDN + 2 * 64 * LDP + 128) * 4;
    const int yoff_smem  = (2 * 64 * LDN + 64) * 4;
    cudaFuncSetAttribute(chunk_kernel, cudaFuncAttributeMaxDynamicSharedMemorySize, chunk_smem);
    cudaFuncSetAttribute(yoff_kernel,  cudaFuncAttributeMaxDynamicSharedMemorySize, yoff_smem);

    // 1) in-projection: gZX = u @ W_in^T   (8192 x 8512 x 2048)
    {
        dim3 grid((DPROJ + GBN - 1) / GBN, TT / GBM);
        gemm_nt_kernel<<<grid, 256>>>(u, W_in, (float*)pZX, TT, DPROJ, DMODEL);
    }
    // 2) dt / dalog
    dt_kernel<<<(TT * NH + 255) / 256, 256>>>(dt_bias, A_log);
    // 3) conv1d + SiLU
    conv_kernel<<<(TT * (CONVDIM / 4) + 255) / 256, 256>>>(conv_w, conv_b);
    // 4) per-chunk Y_diag + local states
    {
        dim3 grid(NBATCH * NCHUNK, NH);
        chunk_kernel<<<grid, 256, chunk_smem>>>();
    }
    // 5) inter-chunk prefix scan
    scan_kernel<<<NBATCH * NH, 512>>>();
    // 6) Y_off + skip + gating
    {
        dim3 grid(NBATCH * NCHUNK, NH);
        yoff_kernel<<<grid, 256, yoff_smem>>>(Dparam);
    }
    // 7) RMSNorm
    rms_kernel<<<TT, 256>>>(norm_w);
    // 8) out-projection: out = y @ W_out^T  (8192 x 2048 x 4096)
    {
        dim3 grid(DMODEL / GBN, TT / GBM);
        gemm_nt_kernel<<<grid, 256>>>((const float*)pYb, W_out, out, TT, DMODEL, DINNER);
    }
}

// round 3
// speedup vs baseline: 1.7349x; 1.7349x over previous
#include <cuda_runtime.h>
#include <cuda_bf16.h>
#include <cstdint>
#include <math.h>

#define TT      8192
#define LSEQ    4096
#define NBATCH  2
#define DMODEL  2048
#define DINNER  4096
#define DSTATE  128
#define DCONV   4
#define NH      64
#define HD      64
#define CHUNKSZ 64
#define NCHUNK  64
#define CONVDIM 4352
#define DPROJ   8512
#define DT_OFF  8448
#define DPROJ_PAD 8704   // 68 * 128

#define K1  DMODEL        // 2048
#define KP1 (3*K1)        // 6144
#define K2  DINNER        // 4096
#define KP2 (3*K2)        // 12288

// ---------------- scratch ------------------------------------------------------
__device__ float gZX[(size_t)TT * DPROJ];
__device__ float gXC[(size_t)TT * CONVDIM];
__device__ float gYb[(size_t)TT * DINNER];
__device__ float gStates[(size_t)NBATCH * NCHUNK * NH * HD * DSTATE];
__device__ float gDt[TT * NH];
__device__ float gDalog[TT * NH];
__device__ float gAsum[NBATCH * NCHUNK * NH];

__device__ __nv_bfloat16 gA1[(size_t)TT * KP1];
__device__ __nv_bfloat16 gB1[(size_t)DPROJ_PAD * KP1];
__device__ __nv_bfloat16 gA2[(size_t)TT * KP2];
__device__ __nv_bfloat16 gB2[(size_t)DMODEL * KP2];

// ================= helpers ======================================================
__device__ __forceinline__ uint32_t smem_u32(const void* p) {
    uint32_t a;
    asm("{ .reg .u64 t; cvta.to.shared.u64 t, %1; cvt.u32.u64 %0, t; }" : "=r"(a) : "l"(p));
    return a;
}
__device__ __forceinline__ void cp16(uint32_t sa, const void* g) {
    asm volatile("cp.async.cg.shared.global [%0], [%1], 16;" :: "r"(sa), "l"(g));
}
__device__ __forceinline__ void ldmx4(uint32_t* r, uint32_t addr) {
    asm volatile("ldmatrix.sync.aligned.m8n8.x4.shared.b16 {%0,%1,%2,%3}, [%4];"
        : "=r"(r[0]), "=r"(r[1]), "=r"(r[2]), "=r"(r[3]) : "r"(addr));
}
__device__ __forceinline__ void mma16816(float* d, const uint32_t* a, const uint32_t* b) {
    asm volatile("mma.sync.aligned.m16n8k16.row.col.f32.bf16.bf16.f32 "
        "{%0,%1,%2,%3}, {%4,%5,%6,%7}, {%8,%9}, {%0,%1,%2,%3};"
        : "+f"(d[0]), "+f"(d[1]), "+f"(d[2]), "+f"(d[3])
        : "r"(a[0]), "r"(a[1]), "r"(a[2]), "r"(a[3]), "r"(b[0]), "r"(b[1]));
}

// ================= warp-MMA GEMM: C[m,n] = sum_k A[m,k]*B[n,k] ==================
// bf16 in, fp32 accum/out. BM=BN=128, BK=32. 8 warps: 2(M) x 4(N), warp = 64x32.
#define ROWH 40                   // halves per smem row (32 + 8 pad)
#define ROWB (ROWH*2)             // 80 bytes
#define TILE_B (128*ROWB)         // 10240
#define STAGE_B (2*TILE_B)        // 20480
#define NSTG 3
#define GM_SMEM (NSTG*STAGE_B)

__global__ __launch_bounds__(256)
void gemm_mma_kernel(const __nv_bfloat16* __restrict__ A, const __nv_bfloat16* __restrict__ B,
                     float* __restrict__ C, int Nreal, int Kp)
{
    extern __shared__ char smem[];
    const uint32_t sb = smem_u32(smem);
    const int tid = threadIdx.x;
    const int wid = tid >> 5;
    const int lane = tid & 31;
    const int m0 = blockIdx.y * 128;
    const int n0 = blockIdx.x * 128;
    const int warp_m = wid & 1;       // 0..1 -> 64 rows
    const int warp_n = wid >> 1;      // 0..3 -> 32 cols
    const int NKB = Kp >> 5;

    float acc[4][4][4];
#pragma unroll
    for (int mi = 0; mi < 4; mi++)
#pragma unroll
        for (int ni = 0; ni < 4; ni++)
#pragma unroll
            for (int r = 0; r < 4; r++) acc[mi][ni][r] = 0.f;

    // loader: A tile 128x32, B tile 128x32 (both K-major), 4 cp16 per thread
    const int lrow = tid >> 2;        // 0..63  -> two rows per thread (x, x+64)
    const int lch  = tid & 3;         // 16B chunk
    auto load_stage = [&](int s, int kb) {
        uint32_t base = sb + s * STAGE_B;
        const __nv_bfloat16* gA = A + (size_t)m0 * Kp + (size_t)kb * 32;
        const __nv_bfloat16* gB = B + (size_t)n0 * Kp + (size_t)kb * 32;
#pragma unroll
        for (int i = 0; i < 2; i++) {
            int row = lrow + i * 64;
            cp16(base + row * ROWB + lch * 16, gA + (size_t)row * Kp + lch * 8);
        }
#pragma unroll
        for (int i = 0; i < 2; i++) {
            int row = lrow + i * 64;
            cp16(base + TILE_B + row * ROWB + lch * 16, gB + (size_t)row * Kp + lch * 8);
        }
        asm volatile("cp.async.commit_group;" ::: "memory");
    };

    // ldmatrix lane address components
    const int a_r  = lane & 15;            // row within m16
    const int a_kq = (lane >> 4) * 8;      // k quadrant
    const int b_n  = ((lane >> 4) << 3) + (lane & 7);  // n within n16
    const int b_kq = ((lane >> 3) & 1) * 8;

    load_stage(0, 0);
    load_stage(1, 1 < NKB ? 1 : 0);

    for (int kb = 0; kb < NKB; kb++) {
        const int s = kb % NSTG;
        if (kb + 1 < NKB) asm volatile("cp.async.wait_group 1;" ::: "memory");
        else              asm volatile("cp.async.wait_group 0;" ::: "memory");
        __syncthreads();

        if (kb + 2 < NKB) load_stage((kb + 2) % NSTG, kb + 2);

        const uint32_t abase = sb + s * STAGE_B;
        const uint32_t bbase = abase + TILE_B;
#pragma unroll
        for (int ks = 0; ks < 2; ks++) {
            const int k0 = ks * 16;
            uint32_t af[4][4], bf[2][4];
#pragma unroll
            for (int mi = 0; mi < 4; mi++) {
                int m = warp_m * 64 + mi * 16 + a_r;
                ldmx4(af[mi], abase + m * ROWB + (k0 + a_kq) * 2);
            }
#pragma unroll
            for (int ni2 = 0; ni2 < 2; ni2++) {
                int n = warp_n * 32 + ni2 * 16 + b_n;
                ldmx4(bf[ni2], bbase + n * ROWB + (k0 + b_kq) * 2);
            }
#pragma unroll
            for (int mi = 0; mi < 4; mi++)
#pragma unroll
                for (int ni = 0; ni < 4; ni++)
                    mma16816(acc[mi][ni], af[mi], &bf[ni >> 1][(ni & 1) * 2]);
        }
        __syncthreads();
    }

    // epilogue
    const int er = lane >> 2;
    const int ec = (lane & 3) * 2;
#pragma unroll
    for (int mi = 0; mi < 4; mi++) {
#pragma unroll
        for (int ni = 0; ni < 4; ni++) {
            int col = n0 + warp_n * 32 + ni * 8 + ec;
            if (col < Nreal) {
                int row = m0 + warp_m * 64 + mi * 16 + er;
                float* p0 = C + (size_t)row * Nreal + col;
                p0[0] = acc[mi][ni][0];
                p0[1] = acc[mi][ni][1];
                float* p1 = p0 + (size_t)8 * Nreal;
                p1[0] = acc[mi][ni][2];
                p1[1] = acc[mi][ni][3];
            }
        }
    }
}

// ================= fp32 -> bf16 hi/lo split (K-folded) ==========================
__global__ __launch_bounds__(256)
void split_a_kernel(const float* __restrict__ src, __nv_bfloat16* __restrict__ dst,
                    int kshift)
{
    size_t i = (size_t)blockIdx.x * blockDim.x + threadIdx.x;
    int K = 1 << kshift;
    int r = (int)(i >> kshift);
    int k = (int)(i & (K - 1));
    float x = src[i];
    __nv_bfloat16 hi = __float2bfloat16(x);
    __nv_bfloat16 lo = __float2bfloat16(x - __bfloat162float(hi));
    size_t base = (size_t)r * 3 * K + k;
    dst[base] = hi; dst[base + K] = lo; dst[base + 2 * K] = hi;
}

__global__ __launch_bounds__(256)
void split_b_kernel(const float* __restrict__ src, __nv_bfloat16* __restrict__ dst,
                    int rows_src, int kshift)
{
    size_t i = (size_t)blockIdx.x * blockDim.x + threadIdx.x;
    int K = 1 << kshift;
    int r = (int)(i >> kshift);
    int k = (int)(i & (K - 1));
    float x = (r < rows_src) ? src[(size_t)r * K + k] : 0.f;
    __nv_bfloat16 hi = __float2bfloat16(x);
    __nv_bfloat16 lo = __float2bfloat16(x - __bfloat162float(hi));
    size_t base = (size_t)r * 3 * K + k;
    dst[base] = hi; dst[base + K] = hi; dst[base + 2 * K] = lo;
}

// ================= pointwise / SSD kernels ======================================
__global__ __launch_bounds__(256)
void dt_kernel(const float* __restrict__ dt_bias, const float* __restrict__ A_log)
{
    int i = blockIdx.x * blockDim.x + threadIdx.x;
    if (i >= TT * NH) return;
    int h = i & (NH - 1);
    int t = i >> 6;
    float x = gZX[(size_t)t * DPROJ + DT_OFF + h] + dt_bias[h];
    float sp = (x > 20.f) ? x : log1pf(__expf(x));
    float A = -__expf(A_log[h]);
    gDt[i] = sp;
    gDalog[i] = sp * A;
}

__global__ __launch_bounds__(256)
void conv_kernel(const float* __restrict__ conv_w, const float* __restrict__ conv_b)
{
    int idx = blockIdx.x * blockDim.x + threadIdx.x;
    const int per_tok = CONVDIM / 4;
    if (idx >= TT * per_tok) return;
    int t  = idx / per_tok;
    int c4 = (idx - t * per_tok) * 4;
    int l  = t & (LSEQ - 1);

    float acc0 = conv_b[c4 + 0];
    float acc1 = conv_b[c4 + 1];
    float acc2 = conv_b[c4 + 2];
    float acc3 = conv_b[c4 + 3];
#pragma unroll
    for (int k = 0; k < DCONV; k++) {
        int lk = l - (DCONV - 1) + k;
        if (lk >= 0) {
            const float4 v = *(const float4*)&gZX[(size_t)(t - (DCONV - 1) + k) * DPROJ + DINNER + c4];
            acc0 += v.x * conv_w[(c4 + 0) * DCONV + k];
            acc1 += v.y * conv_w[(c4 + 1) * DCONV + k];
            acc2 += v.z * conv_w[(c4 + 2) * DCONV + k];
            acc3 += v.w * conv_w[(c4 + 3) * DCONV + k];
        }
    }
    float* o = &gXC[(size_t)t * CONVDIM + c4];
    o[0] = acc0 / (1.f + __expf(-acc0));
    o[1] = acc1 / (1.f + __expf(-acc1));
    o[2] = acc2 / (1.f + __expf(-acc2));
    o[3] = acc3 / (1.f + __expf(-acc3));
}

#define LDN 129
#define LDP 65

__global__ __launch_bounds__(256)
void chunk_kernel()
{
    extern __shared__ float sm[];
    float* sB   = sm;
    float* sC   = sB + 64 * LDN;
    float* sX   = sC + 64 * LDN;
    float* sM   = sX + 64 * LDP;
    float* sAcs = sM + 64 * LDP;
    float* sDec = sAcs + 64;

    const int bc = blockIdx.x;
    const int h  = blockIdx.y;
    const int tid = threadIdx.x;
    const int t0 = bc * CHUNKSZ;

    if (tid < 64) sAcs[tid] = gDalog[(size_t)(t0 + tid) * NH + h];
    __syncthreads();
    if (tid == 0) {
        float s = 0.f;
        for (int l = 0; l < 64; l++) { s += sAcs[l]; sAcs[l] = s; }
    }
    __syncthreads();
    if (tid < 64) sDec[tid] = __expf(sAcs[63] - sAcs[tid]);

    for (int i = tid; i < 2048; i += 256) {
        int s  = i >> 5;
        int c4 = (i & 31) << 2;
        const float* row = &gXC[(size_t)(t0 + s) * CONVDIM];
        float4 vb = *(const float4*)(row + DINNER + c4);
        float4 vc = *(const float4*)(row + DINNER + DSTATE + c4);
        sB[s * LDN + c4 + 0] = vb.x; sB[s * LDN + c4 + 1] = vb.y;
        sB[s * LDN + c4 + 2] = vb.z; sB[s * LDN + c4 + 3] = vb.w;
        sC[s * LDN + c4 + 0] = vc.x; sC[s * LDN + c4 + 1] = vc.y;
        sC[s * LDN + c4 + 2] = vc.z; sC[s * LDN + c4 + 3] = vc.w;
    }
    for (int i = tid; i < 1024; i += 256) {
        int s  = i >> 4;
        int c4 = (i & 15) << 2;
        float d = gDt[(size_t)(t0 + s) * NH + h];
        float4 v = *(const float4*)(&gXC[(size_t)(t0 + s) * CONVDIM + h * HD + c4]);
        sX[s * LDP + c4 + 0] = v.x * d; sX[s * LDP + c4 + 1] = v.y * d;
        sX[s * LDP + c4 + 2] = v.z * d; sX[s * LDP + c4 + 3] = v.w * d;
    }
    __syncthreads();

    const int tx = tid & 15;
    const int ty = tid >> 4;

    {
        float acc[4][4];
#pragma unroll
        for (int i = 0; i < 4; i++)
#pragma unroll
            for (int j = 0; j < 4; j++) acc[i][j] = 0.f;
        for (int n = 0; n < 128; n++) {
            float a[4], b[4];
#pragma unroll
            for (int i = 0; i < 4; i++) a[i] = sC[(ty * 4 + i) * LDN + n];
#pragma unroll
            for (int j = 0; j < 4; j++) b[j] = sB[(tx * 4 + j) * LDN + n];
#pragma unroll
            for (int i = 0; i < 4; i++)
#pragma unroll
                for (int j = 0; j < 4; j++) acc[i][j] += a[i] * b[j];
        }
#pragma unroll
        for (int i = 0; i < 4; i++)
#pragma unroll
            for (int j = 0; j < 4; j++)
                sM[(ty * 4 + i) * LDP + tx * 4 + j] = acc[i][j];
    }
    __syncthreads();

    for (int i = tid; i < 4096; i += 256) {
        int l = i >> 6, s = i & 63;
        float v = (s <= l) ? sM[l * LDP + s] * __expf(sAcs[l] - sAcs[s]) : 0.f;
        sM[l * LDP + s] = v;
    }
    __syncthreads();

    {
        float acc[4][4];
#pragma unroll
        for (int i = 0; i < 4; i++)
#pragma unroll
            for (int j = 0; j < 4; j++) acc[i][j] = 0.f;
        for (int s = 0; s < 64; s++) {
            float w[4], xv[4];
#pragma unroll
            for (int i = 0; i < 4; i++) w[i] = sM[(ty * 4 + i) * LDP + s];
#pragma unroll
            for (int j = 0; j < 4; j++) xv[j] = sX[s * LDP + tx * 4 + j];
#pragma unroll
            for (int i = 0; i < 4; i++)
#pragma unroll
                for (int j = 0; j < 4; j++) acc[i][j] += w[i] * xv[j];
        }
#pragma unroll
        for (int i = 0; i < 4; i++) {
            int l = ty * 4 + i;
#pragma unroll
            for (int j = 0; j < 4; j++) {
                int p = tx * 4 + j;
                gYb[(size_t)(t0 + l) * DINNER + h * HD + p] = acc[i][j];
            }
        }
    }

    {
        float st[4][8];
#pragma unroll
        for (int i = 0; i < 4; i++)
#pragma unroll
            for (int j = 0; j < 8; j++) st[i][j] = 0.f;
        const int pb = ty * 4, nb = tx * 8;
        for (int s = 0; s < 64; s++) {
            float d = sDec[s];
            float xv[4], bv[8];
#pragma unroll
            for (int i = 0; i < 4; i++) xv[i] = sX[s * LDP + pb + i] * d;
#pragma unroll
            for (int j = 0; j < 8; j++) bv[j] = sB[s * LDN + nb + j];
#pragma unroll
            for (int i = 0; i < 4; i++)
#pragma unroll
                for (int j = 0; j < 8; j++) st[i][j] += xv[i] * bv[j];
        }
        size_t base = ((size_t)bc * NH + h) * (HD * DSTATE);
#pragma unroll
        for (int i = 0; i < 4; i++)
#pragma unroll
            for (int j = 0; j < 8; j++)
                gStates[base + (size_t)(pb + i) * DSTATE + nb + j] = st[i][j];
    }

    if (tid == 0) gAsum[bc * NH + h] = sAcs[63];
}

__global__ __launch_bounds__(512)
void scan_kernel()
{
    const int bh = blockIdx.x;
    const int b = bh >> 6, h = bh & 63;
    const int tid = threadIdx.x;
    const int off = tid * 16;

    float4 prev[4];
#pragma unroll
    for (int q = 0; q < 4; q++) prev[q] = make_float4(0.f, 0.f, 0.f, 0.f);

    for (int c = 0; c < NCHUNK; c++) {
        int bc = b * NCHUNK + c;
        size_t base = ((size_t)bc * NH + h) * (HD * DSTATE) + off;
        float dec = __expf(gAsum[bc * NH + h]);
        float4 cur[4];
#pragma unroll
        for (int q = 0; q < 4; q++) cur[q] = *(float4*)&gStates[base + q * 4];
#pragma unroll
        for (int q = 0; q < 4; q++) *(float4*)&gStates[base + q * 4] = prev[q];
#pragma unroll
        for (int q = 0; q < 4; q++) {
            prev[q].x = prev[q].x * dec + cur[q].x;
            prev[q].y = prev[q].y * dec + cur[q].y;
            prev[q].z = prev[q].z * dec + cur[q].z;
            prev[q].w = prev[q].w * dec + cur[q].w;
        }
    }
}

__global__ __launch_bounds__(256)
void yoff_kernel(const float* __restrict__ Dparam)
{
    extern __shared__ float sm[];
    float* sC   = sm;
    float* sSt  = sC + 64 * LDN;
    float* sAcs = sSt + 64 * LDN;

    const int bc = blockIdx.x;
    const int h  = blockIdx.y;
    const int tid = threadIdx.x;
    const int t0 = bc * CHUNKSZ;

    if (tid < 64) sAcs[tid] = gDalog[(size_t)(t0 + tid) * NH + h];
    __syncthreads();
    if (tid == 0) {
        float s = 0.f;
        for (int l = 0; l < 64; l++) { s += sAcs[l]; sAcs[l] = s; }
    }

    for (int i = tid; i < 2048; i += 256) {
        int s  = i >> 5;
        int c4 = (i & 31) << 2;
        float4 vc = *(const float4*)(&gXC[(size_t)(t0 + s) * CONVDIM + DINNER + DSTATE + c4]);
        sC[s * LDN + c4 + 0] = vc.x; sC[s * LDN + c4 + 1] = vc.y;
        sC[s * LDN + c4 + 2] = vc.z; sC[s * LDN + c4 + 3] = vc.w;
        float4 vs = *(const float4*)(&gStates[(((size_t)bc * NH + h) * HD + s) * DSTATE + c4]);
        sSt[s * LDN + c4 + 0] = vs.x; sSt[s * LDN + c4 + 1] = vs.y;
        sSt[s * LDN + c4 + 2] = vs.z; sSt[s * LDN + c4 + 3] = vs.w;
    }
    __syncthreads();

    const int tx = tid & 15;
    const int ty = tid >> 4;

    float acc[4][4];
#pragma unroll
    for (int i = 0; i < 4; i++)
#pragma unroll
        for (int j = 0; j < 4; j++) acc[i][j] = 0.f;
    for (int n = 0; n < 128; n++) {
        float cv[4], sv[4];
#pragma unroll
        for (int i = 0; i < 4; i++) cv[i] = sC[(ty * 4 + i) * LDN + n];
#pragma unroll
        for (int j = 0; j < 4; j++) sv[j] = sSt[(tx * 4 + j) * LDN + n];
#pragma unroll
        for (int i = 0; i < 4; i++)
#pragma unroll
            for (int j = 0; j < 4; j++) acc[i][j] += cv[i] * sv[j];
    }

    const float Dh = Dparam[h];
#pragma unroll
    for (int i = 0; i < 4; i++) {
        int l = ty * 4 + i;
        float sdo = __expf(sAcs[l]);
        size_t tz = (size_t)(t0 + l);
#pragma unroll
        for (int j = 0; j < 4; j++) {
            int p = tx * 4 + j;
            float x = gXC[tz * CONVDIM + h * HD + p];
            float z = gZX[tz * DPROJ + h * HD + p];
            float y = gYb[tz * DINNER + h * HD + p] + sdo * acc[i][j] + x * Dh;
            y *= z / (1.f + __expf(-z));
            gYb[tz * DINNER + h * HD + p] = y;
        }
    }
}

__global__ __launch_bounds__(256)
void rms_kernel(const float* __restrict__ norm_w)
{
    const int t = blockIdx.x;
    const int tid = threadIdx.x;
    float* y = &gYb[(size_t)t * DINNER];

    float ss = 0.f;
    for (int i = tid * 4; i < DINNER; i += 256 * 4) {
        float4 v = *(const float4*)(y + i);
        ss += v.x * v.x + v.y * v.y + v.z * v.z + v.w * v.w;
    }
#pragma unroll
    for (int o = 16; o > 0; o >>= 1) ss += __shfl_down_sync(0xffffffffu, ss, o);

    __shared__ float red[8];
    if ((tid & 31) == 0) red[tid >> 5] = ss;
    __syncthreads();
    if (tid == 0) {
        float tot = 0.f;
#pragma unroll
        for (int w = 0; w < 8; w++) tot += red[w];
        red[0] = rsqrtf(tot / (float)DINNER + 1e-5f);
    }
    __syncthreads();
    const float scale = red[0];

    for (int i = tid * 4; i < DINNER; i += 256 * 4) {
        float4 v = *(const float4*)(y + i);
        float4 w = *(const float4*)(norm_w + i);
        v.x *= scale * w.x; v.y *= scale * w.y;
        v.z *= scale * w.z; v.w *= scale * w.w;
        *(float4*)(y + i) = v;
    }
}

// ================= launch =======================================================
extern "C" void kernel_launch(void* const* d_in, const int* in_sizes, int n_in,
                              void* d_out, int out_size)
{
    const float* u       = (const float*)d_in[0];
    const float* W_in    = (const float*)d_in[1];
    const float* conv_w  = (const float*)d_in[2];
    const float* conv_b  = (const float*)d_in[3];
    const float* dt_bias = (const float*)d_in[4];
    const float* A_log   = (const float*)d_in[5];
    const float* Dparam  = (const float*)d_in[6];
    const float* norm_w  = (const float*)d_in[7];
    const float* W_out   = (const float*)d_in[8];
    float* out = (float*)d_out;

    void *pZX, *pYb, *pA1, *pB1, *pA2, *pB2;
    cudaGetSymbolAddress(&pZX, gZX);
    cudaGetSymbolAddress(&pYb, gYb);
    cudaGetSymbolAddress(&pA1, gA1);
    cudaGetSymbolAddress(&pB1, gB1);
    cudaGetSymbolAddress(&pA2, gA2);
    cudaGetSymbolAddress(&pB2, gB2);

    const int chunk_smem = (2 * 64 * LDN + 2 * 64 * LDP + 128) * 4;
    const int yoff_smem  = (2 * 64 * LDN + 64) * 4;
    cudaFuncSetAttribute(chunk_kernel, cudaFuncAttributeMaxDynamicSharedMemorySize, chunk_smem);
    cudaFuncSetAttribute(yoff_kernel,  cudaFuncAttributeMaxDynamicSharedMemorySize, yoff_smem);
    cudaFuncSetAttribute(gemm_mma_kernel, cudaFuncAttributeMaxDynamicSharedMemorySize, GM_SMEM);

    // 0) bf16 hi/lo splits for GEMM1 operands
    split_a_kernel<<<(int)(((size_t)TT * K1) / 256), 256>>>(u, (__nv_bfloat16*)pA1, 11);
    split_b_kernel<<<(int)(((size_t)DPROJ_PAD * K1) / 256), 256>>>(W_in, (__nv_bfloat16*)pB1, DPROJ, 11);

    // 1) in-projection (mma.sync bf16): gZX = u @ W_in^T
    {
        dim3 grid(DPROJ_PAD / 128, TT / 128);
        gemm_mma_kernel<<<grid, 256, GM_SMEM>>>((const __nv_bfloat16*)pA1, (const __nv_bfloat16*)pB1,
                                                (float*)pZX, DPROJ, KP1);
    }
    // 2) dt / dalog
    dt_kernel<<<(TT * NH + 255) / 256, 256>>>(dt_bias, A_log);
    // 3) conv1d + SiLU
    conv_kernel<<<(TT * (CONVDIM / 4) + 255) / 256, 256>>>(conv_w, conv_b);
    // 4) per-chunk Y_diag + local states
    {
        dim3 grid(NBATCH * NCHUNK, NH);
        chunk_kernel<<<grid, 256, chunk_smem>>>();
    }
    // 5) inter-chunk prefix scan
    scan_kernel<<<NBATCH * NH, 512>>>();
    // 6) Y_off + skip + gating
    {
        dim3 grid(NBATCH * NCHUNK, NH);
        yoff_kernel<<<grid, 256, yoff_smem>>>(Dparam);
    }
    // 7) RMSNorm
    rms_kernel<<<TT, 256>>>(norm_w);
    // 8) bf16 hi/lo splits for GEMM2 operands
    split_a_kernel<<<(int)(((size_t)TT * K2) / 256), 256>>>((const float*)pYb, (__nv_bfloat16*)pA2, 12);
    split_b_kernel<<<(int)(((size_t)DMODEL * K2) / 256), 256>>>(W_out, (__nv_bfloat16*)pB2, DMODEL, 12);
    // 9) out-projection (mma.sync bf16): out = y @ W_out^T
    {
        dim3 grid(DMODEL / 128, TT / 128);
        gemm_mma_kernel<<<grid, 256, GM_SMEM>>>((const __nv_bfloat16*)pA2, (const __nv_bfloat16*)pB2,
                                                out, DMODEL, KP2);
    }
}